// round 14
// baseline (speedup 1.0000x reference)
#include <cuda_runtime.h>
#include <cuda_bf16.h>

// Problem constants (fixed by the dataset)
#define B    256
#define G    20000
#define NTF  1024
#define NPT  8     // nodes per TF
#define GPT  64    // genes per TF
#define EPS  1e-5f
#define SLOPE 0.01f

// Scratch: x transposed to [G, B] for coalesced gene-row gathers. 20.48 MB.
__device__ float g_xT[(size_t)G * B];

// ---------------------------------------------------------------------------
// Kernel 1: transpose x [B, G] -> xT [G, B].  G = 625 * 32 exactly.
// ---------------------------------------------------------------------------
__global__ void __launch_bounds__(256) transpose_kernel(const float* __restrict__ x) {
    __shared__ float tile[32][33];
    const int g0 = blockIdx.x * 32;
    const int b0 = blockIdx.y * 32;
    const int tx = threadIdx.x;      // 0..31
    const int ty = threadIdx.y;      // 0..7

#pragma unroll
    for (int i = 0; i < 32; i += 8)
        tile[ty + i][tx] = x[(size_t)(b0 + ty + i) * G + (g0 + tx)];
    __syncthreads();
#pragma unroll
    for (int i = 0; i < 32; i += 8)
        g_xT[(size_t)(g0 + ty + i) * B + (b0 + tx)] = tile[tx][ty + i];
}

// ---------------------------------------------------------------------------
// Kernel 2: fused encoder. One 256-thread block per TF (grid = 1024).
//   Mainloop: half-block h (128 thr) accumulates genes [32h, 32h+32) for
//   batch pair ht, with R12's deep MLP16 prefetch (16 gathers in flight).
//   Exchange: partials through smem; thread tid then owns single batch
//   element b=tid with the full 64-gene sum -> epilogue on ALL 256 threads.
//   layer1 -> BN1 -> LeakyReLU -> layer2 -> BN2 -> LeakyReLU -> out.
// ---------------------------------------------------------------------------
__global__ void __launch_bounds__(256, 4) fused_encoder_kernel(
    const float* __restrict__ w1,
    const int*   __restrict__ in_idx1,
    const float* __restrict__ w2,
    float*       __restrict__ out)
{
    const int tid  = threadIdx.x;     // 0..255
    const int h    = tid >> 7;        // gene-half 0/1
    const int ht   = tid & 127;       // batch-pair id within half
    const int wrp  = tid >> 5;        // 0..7
    const int lane = tid & 31;
    const int t    = blockIdx.x;

    __shared__ __align__(16) float  sw1t[NPT * GPT];   // [g*8 + j]
    __shared__ int    sg[GPT];                         // gene offsets * B
    __shared__ float  sw2[NPT];
    __shared__ __align__(16) float2 sacc[256][NPT];    // partial exchange (16 KB)
    __shared__ float  rsum[8][NPT + 2];
    __shared__ float  rsq [8][NPT + 2];
    __shared__ float  smean[NPT], srstd[NPT];
    __shared__ float  zmean, zrstd;

    // ---- Stage weights (transposed to [gene][node]) + gene indices -----------
#pragma unroll
    for (int i = tid; i < NPT * GPT; i += 256) {
        const int j = i >> 6;          // node
        const int g = i & 63;          // gene slot
        sw1t[g * NPT + j] = w1[t * (NPT * GPT) + i];
    }
    if (tid < GPT) sg[tid]  = in_idx1[t * (NPT * GPT) + tid] * B;
    if (tid < NPT) sw2[tid] = w2[t * NPT + tid];
    __syncthreads();

    // ---- Layer 1 mainloop: 32 genes per half, MLP16 prefetch -----------------
    float2 acc[NPT];
#pragma unroll
    for (int j = 0; j < NPT; j++) acc[j] = make_float2(0.f, 0.f);

    const int boff  = 2 * ht;
    const int gbase = h * (GPT / 2);   // 0 or 32

#define GENE8_FMA(gb, xv)                                                      \
    {                                                                          \
        _Pragma("unroll")                                                      \
        for (int u = 0; u < 8; u++) {                                          \
            const float4 wa = *(const float4*)&sw1t[((gb) + u) * NPT];         \
            const float4 wb = *(const float4*)&sw1t[((gb) + u) * NPT + 4];     \
            acc[0].x = fmaf(wa.x, xv[u].x, acc[0].x);                          \
            acc[0].y = fmaf(wa.x, xv[u].y, acc[0].y);                          \
            acc[1].x = fmaf(wa.y, xv[u].x, acc[1].x);                          \
            acc[1].y = fmaf(wa.y, xv[u].y, acc[1].y);                          \
            acc[2].x = fmaf(wa.z, xv[u].x, acc[2].x);                          \
            acc[2].y = fmaf(wa.z, xv[u].y, acc[2].y);                          \
            acc[3].x = fmaf(wa.w, xv[u].x, acc[3].x);                          \
            acc[3].y = fmaf(wa.w, xv[u].y, acc[3].y);                          \
            acc[4].x = fmaf(wb.x, xv[u].x, acc[4].x);                          \
            acc[4].y = fmaf(wb.x, xv[u].y, acc[4].y);                          \
            acc[5].x = fmaf(wb.y, xv[u].x, acc[5].x);                          \
            acc[5].y = fmaf(wb.y, xv[u].y, acc[5].y);                          \
            acc[6].x = fmaf(wb.z, xv[u].x, acc[6].x);                          \
            acc[6].y = fmaf(wb.z, xv[u].y, acc[6].y);                          \
            acc[7].x = fmaf(wb.w, xv[u].x, acc[7].x);                          \
            acc[7].y = fmaf(wb.w, xv[u].y, acc[7].y);                          \
        }                                                                      \
    }

    {
        float2 xa[8], xb[8];
#pragma unroll
        for (int u = 0; u < 8; u++)
            xa[u] = *(const float2*)&g_xT[sg[gbase + u] + boff];
#pragma unroll
        for (int u = 0; u < 8; u++)
            xb[u] = *(const float2*)&g_xT[sg[gbase + 8 + u] + boff];

        // consume 0..7, refill 16..23, consume 8..15, refill 24..31,
        // consume 16..23, consume 24..31
        GENE8_FMA(gbase, xa);
#pragma unroll
        for (int u = 0; u < 8; u++)
            xa[u] = *(const float2*)&g_xT[sg[gbase + 16 + u] + boff];
        GENE8_FMA(gbase + 8, xb);
#pragma unroll
        for (int u = 0; u < 8; u++)
            xb[u] = *(const float2*)&g_xT[sg[gbase + 24 + u] + boff];
        GENE8_FMA(gbase + 16, xa);
        GENE8_FMA(gbase + 24, xb);
    }

    // ---- Exchange: write partials, re-map to thread-per-batch-element --------
#pragma unroll
    for (int j = 0; j < NPT; j++) sacc[tid][j] = acc[j];
    __syncthreads();

    float a[NPT];
    {
        const int p  = tid >> 1;       // batch pair
        const int hi = tid & 1;        // element within pair
#pragma unroll
        for (int j = 0; j < NPT; j++) {
            const float2 p0 = sacc[p][j];          // half-0 partial
            const float2 p1 = sacc[128 + p][j];    // half-1 partial
            a[j] = hi ? (p0.y + p1.y) : (p0.x + p1.x);
        }
    }

    // ---- BN1 stats over 256 batch elems (1 per thread) -----------------------
#pragma unroll
    for (int j = 0; j < NPT; j++) {
        float s  = a[j];
        float s2 = a[j] * a[j];
#pragma unroll
        for (int o = 16; o > 0; o >>= 1) {
            s  += __shfl_xor_sync(0xffffffffu, s,  o);
            s2 += __shfl_xor_sync(0xffffffffu, s2, o);
        }
        if (lane == 0) { rsum[wrp][j] = s; rsq[wrp][j] = s2; }
    }
    __syncthreads();
    if (tid < NPT) {
        float s = 0.f, s2 = 0.f;
#pragma unroll
        for (int w = 0; w < 8; w++) { s += rsum[w][tid]; s2 += rsq[w][tid]; }
        const float m   = s * (1.f / B);
        const float var = s2 * (1.f / B) - m * m;
        smean[tid] = m;
        srstd[tid] = rsqrtf(var + EPS);
    }
    __syncthreads();

    // ---- BN1 + LeakyReLU + Layer 2 dot ---------------------------------------
    float z = 0.f;
#pragma unroll
    for (int j = 0; j < NPT; j++) {
        float v = (a[j] - smean[j]) * srstd[j];
        v = (v > 0.f) ? v : SLOPE * v;
        z = fmaf(sw2[j], v, z);
    }

    // ---- BN2 stats over the 256 batch values ---------------------------------
    {
        float s = z, s2 = z * z;
#pragma unroll
        for (int o = 16; o > 0; o >>= 1) {
            s  += __shfl_xor_sync(0xffffffffu, s,  o);
            s2 += __shfl_xor_sync(0xffffffffu, s2, o);
        }
        if (lane == 0) { rsum[wrp][NPT] = s; rsq[wrp][NPT] = s2; }
    }
    __syncthreads();
    if (tid == 0) {
        float s = 0.f, s2 = 0.f;
#pragma unroll
        for (int w = 0; w < 8; w++) { s += rsum[w][NPT]; s2 += rsq[w][NPT]; }
        const float m   = s * (1.f / B);
        const float var = s2 * (1.f / B) - m * m;
        zmean = m;
        zrstd = rsqrtf(var + EPS);
    }
    __syncthreads();

    float v = (z - zmean) * zrstd;
    v = (v > 0.f) ? v : SLOPE * v;
    out[(size_t)tid * NTF + t] = v;   // out[b, t]
}

// ---------------------------------------------------------------------------
extern "C" void kernel_launch(void* const* d_in, const int* in_sizes, int n_in,
                              void* d_out, int out_size) {
    const float* x       = (const float*)d_in[0];
    const float* w1      = (const float*)d_in[1];
    const int*   in_idx1 = (const int*)  d_in[2];
    const float* w2      = (const float*)d_in[4];
    float*       out     = (float*)d_out;

    dim3 tb(32, 8);
    dim3 tg(G / 32, B / 32);           // 625 x 8, exact
    transpose_kernel<<<tg, tb>>>(x);
    fused_encoder_kernel<<<NTF, 256>>>(w1, in_idx1, w2, out);
}

// round 15
// speedup vs baseline: 1.3407x; 1.3407x over previous
#include <cuda_runtime.h>
#include <cuda_bf16.h>

// Problem constants (fixed by the dataset)
#define B    256
#define G    20000
#define NTF  1024
#define NPT  8     // nodes per TF
#define GPT  64    // genes per TF
#define EPS  1e-5f
#define SLOPE 0.01f

// Scratch: x transposed to [G, B] for coalesced gene-row gathers. 20.48 MB.
__device__ float g_xT[(size_t)G * B];

// ---------------------------------------------------------------------------
// Kernel 1: transpose x [B, G] -> xT [G, B].  G = 625 * 32 exactly.
// ---------------------------------------------------------------------------
__global__ void __launch_bounds__(256) transpose_kernel(const float* __restrict__ x) {
    __shared__ float tile[32][33];
    const int g0 = blockIdx.x * 32;
    const int b0 = blockIdx.y * 32;
    const int tx = threadIdx.x;      // 0..31
    const int ty = threadIdx.y;      // 0..7

#pragma unroll
    for (int i = 0; i < 32; i += 8)
        tile[ty + i][tx] = x[(size_t)(b0 + ty + i) * G + (g0 + tx)];
    __syncthreads();
#pragma unroll
    for (int i = 0; i < 32; i += 8)
        g_xT[(size_t)(g0 + ty + i) * B + (b0 + tx)] = tile[tx][ty + i];
}

// ---------------------------------------------------------------------------
// Kernel 2: fused encoder. One 128-thread block per TF (grid = 1024).
//   Each thread owns 2 batch elements (float2). Triple-buffered gather
//   prefetch: 24 LDG.64 in flight per thread (MLP~24, 48 lines/warp,
//   under the ~55 per-warp outstanding-LDG cap). Occupancy is grid-limited
//   (6.9 blocks/SM), so prefetch registers are free.
//   layer1 -> BN1 -> LeakyReLU -> layer2 -> BN2 -> LeakyReLU -> out.
// ---------------------------------------------------------------------------
__global__ void __launch_bounds__(128, 6) fused_encoder_kernel(
    const float* __restrict__ w1,
    const int*   __restrict__ in_idx1,
    const float* __restrict__ w2,
    float*       __restrict__ out)
{
    const int tid  = threadIdx.x;     // 0..127
    const int wrp  = tid >> 5;        // 0..3
    const int lane = tid & 31;
    const int t    = blockIdx.x;

    __shared__ __align__(16) float sw1t[NPT * GPT];  // transposed: [g*8 + j]
    __shared__ int   sg[GPT];                        // gene offsets * B
    __shared__ float sw2[NPT];
    __shared__ float rsum[4][NPT + 2];               // per-warp partials
    __shared__ float rsq [4][NPT + 2];
    __shared__ float smean[NPT], srstd[NPT];
    __shared__ float zmean, zrstd;

    // ---- Stage weights (transposed to [gene][node]) + gene indices -----------
#pragma unroll
    for (int i = tid; i < NPT * GPT; i += 128) {
        const int j = i >> 6;          // node
        const int g = i & 63;          // gene slot
        sw1t[g * NPT + j] = w1[t * (NPT * GPT) + i];
    }
    if (tid < GPT) sg[tid]  = in_idx1[t * (NPT * GPT) + tid] * B;
    if (tid < NPT) sw2[tid] = w2[t * NPT + tid];
    __syncthreads();

    // ---- Layer 1: acc[j] (float2 over 2 batch elems) -------------------------
    float2 acc[NPT];
#pragma unroll
    for (int j = 0; j < NPT; j++) acc[j] = make_float2(0.f, 0.f);

    const int boff = 2 * tid;

#define GENE8_FMA(gbase, xv)                                                   \
    {                                                                          \
        _Pragma("unroll")                                                      \
        for (int u = 0; u < 8; u++) {                                          \
            const float4 wa = *(const float4*)&sw1t[((gbase) + u) * NPT];      \
            const float4 wb = *(const float4*)&sw1t[((gbase) + u) * NPT + 4];  \
            acc[0].x = fmaf(wa.x, xv[u].x, acc[0].x);                          \
            acc[0].y = fmaf(wa.x, xv[u].y, acc[0].y);                          \
            acc[1].x = fmaf(wa.y, xv[u].x, acc[1].x);                          \
            acc[1].y = fmaf(wa.y, xv[u].y, acc[1].y);                          \
            acc[2].x = fmaf(wa.z, xv[u].x, acc[2].x);                          \
            acc[2].y = fmaf(wa.z, xv[u].y, acc[2].y);                          \
            acc[3].x = fmaf(wa.w, xv[u].x, acc[3].x);                          \
            acc[3].y = fmaf(wa.w, xv[u].y, acc[3].y);                          \
            acc[4].x = fmaf(wb.x, xv[u].x, acc[4].x);                          \
            acc[4].y = fmaf(wb.x, xv[u].y, acc[4].y);                          \
            acc[5].x = fmaf(wb.y, xv[u].x, acc[5].x);                          \
            acc[5].y = fmaf(wb.y, xv[u].y, acc[5].y);                          \
            acc[6].x = fmaf(wb.z, xv[u].x, acc[6].x);                          \
            acc[6].y = fmaf(wb.z, xv[u].y, acc[6].y);                          \
            acc[7].x = fmaf(wb.w, xv[u].x, acc[7].x);                          \
            acc[7].y = fmaf(wb.w, xv[u].y, acc[7].y);                          \
        }                                                                      \
    }

    float2 xa[8], xb[8], xc[8];
    // prime: genes 0..23 in flight together (MLP ~24)
#pragma unroll
    for (int u = 0; u < 8; u++)
        xa[u] = *(const float2*)&g_xT[sg[u] + boff];
#pragma unroll
    for (int u = 0; u < 8; u++)
        xb[u] = *(const float2*)&g_xT[sg[8 + u] + boff];
#pragma unroll
    for (int u = 0; u < 8; u++)
        xc[u] = *(const float2*)&g_xT[sg[16 + u] + boff];

    // consume a(0-7), refill a<-24-31; consume b(8-15), refill b<-32-39;
    // consume c(16-23), refill c<-40-47; consume a(24-31), refill a<-48-55;
    // consume b(32-39), refill b<-56-63; consume c(40-47);
    // consume a(48-55); consume b(56-63).
    GENE8_FMA(0, xa);
#pragma unroll
    for (int u = 0; u < 8; u++) xa[u] = *(const float2*)&g_xT[sg[24 + u] + boff];
    GENE8_FMA(8, xb);
#pragma unroll
    for (int u = 0; u < 8; u++) xb[u] = *(const float2*)&g_xT[sg[32 + u] + boff];
    GENE8_FMA(16, xc);
#pragma unroll
    for (int u = 0; u < 8; u++) xc[u] = *(const float2*)&g_xT[sg[40 + u] + boff];
    GENE8_FMA(24, xa);
#pragma unroll
    for (int u = 0; u < 8; u++) xa[u] = *(const float2*)&g_xT[sg[48 + u] + boff];
    GENE8_FMA(32, xb);
#pragma unroll
    for (int u = 0; u < 8; u++) xb[u] = *(const float2*)&g_xT[sg[56 + u] + boff];
    GENE8_FMA(40, xc);
    GENE8_FMA(48, xa);
    GENE8_FMA(56, xb);

    // ---- BN1 stats: sum over 256 batch elems (128 threads x 2) per node ------
#pragma unroll
    for (int j = 0; j < NPT; j++) {
        float s  = acc[j].x + acc[j].y;
        float s2 = acc[j].x * acc[j].x + acc[j].y * acc[j].y;
#pragma unroll
        for (int o = 16; o > 0; o >>= 1) {
            s  += __shfl_xor_sync(0xffffffffu, s,  o);
            s2 += __shfl_xor_sync(0xffffffffu, s2, o);
        }
        if (lane == 0) { rsum[wrp][j] = s; rsq[wrp][j] = s2; }
    }
    __syncthreads();
    if (tid < NPT) {
        float s = 0.f, s2 = 0.f;
#pragma unroll
        for (int w = 0; w < 4; w++) { s += rsum[w][tid]; s2 += rsq[w][tid]; }
        const float m   = s * (1.f / B);
        const float var = s2 * (1.f / B) - m * m;
        smean[tid] = m;
        srstd[tid] = rsqrtf(var + EPS);
    }
    __syncthreads();

    // ---- BN1 + LeakyReLU + Layer 2 dot ---------------------------------------
    float z0 = 0.f, z1 = 0.f;
#pragma unroll
    for (int j = 0; j < NPT; j++) {
        const float m = smean[j], r = srstd[j], w = sw2[j];
        float v0 = (acc[j].x - m) * r;  v0 = (v0 > 0.f) ? v0 : SLOPE * v0;
        float v1 = (acc[j].y - m) * r;  v1 = (v1 > 0.f) ? v1 : SLOPE * v1;
        z0 = fmaf(w, v0, z0);
        z1 = fmaf(w, v1, z1);
    }

    // ---- BN2 stats over 256 batch values -------------------------------------
    {
        float s = z0 + z1, s2 = z0 * z0 + z1 * z1;
#pragma unroll
        for (int o = 16; o > 0; o >>= 1) {
            s  += __shfl_xor_sync(0xffffffffu, s,  o);
            s2 += __shfl_xor_sync(0xffffffffu, s2, o);
        }
        if (lane == 0) { rsum[wrp][NPT] = s; rsq[wrp][NPT] = s2; }
    }
    __syncthreads();
    if (tid == 0) {
        float s = 0.f, s2 = 0.f;
#pragma unroll
        for (int w = 0; w < 4; w++) { s += rsum[w][NPT]; s2 += rsq[w][NPT]; }
        const float m   = s * (1.f / B);
        const float var = s2 * (1.f / B) - m * m;
        zmean = m;
        zrstd = rsqrtf(var + EPS);
    }
    __syncthreads();

    const float m = zmean, r = zrstd;
    float v0 = (z0 - m) * r;  v0 = (v0 > 0.f) ? v0 : SLOPE * v0;
    float v1 = (z1 - m) * r;  v1 = (v1 > 0.f) ? v1 : SLOPE * v1;
    out[(size_t)(boff)     * NTF + t] = v0;
    out[(size_t)(boff + 1) * NTF + t] = v1;
}

// ---------------------------------------------------------------------------
extern "C" void kernel_launch(void* const* d_in, const int* in_sizes, int n_in,
                              void* d_out, int out_size) {
    const float* x       = (const float*)d_in[0];
    const float* w1      = (const float*)d_in[1];
    const int*   in_idx1 = (const int*)  d_in[2];
    const float* w2      = (const float*)d_in[4];
    float*       out     = (float*)d_out;

    dim3 tb(32, 8);
    dim3 tg(G / 32, B / 32);           // 625 x 8, exact
    transpose_kernel<<<tg, tb>>>(x);
    fused_encoder_kernel<<<NTF, 128>>>(w1, in_idx1, w2, out);
}